// round 1
// baseline (speedup 1.0000x reference)
#include <cuda_runtime.h>
#include <cstdint>

// Problem constants
#define TREE_DEPTH 13
#define N_NODES 8191            // 2^13 - 1
#define N_EDGES 8190
#define MAX_LEN 16381           // N_NODES + N_EDGES
#define BATCH 8
#define DM 256
#define KMSG 768
#define N_INTERNAL 4095         // nodes 0..4094 get updated
#define TOK_STRIDE (BATCH * DM) // 2048 floats per token

// GEMM tiling
#define BM 128
#define BN 128
#define BK 16
#define TM 8
#define TN 8
#define NTHREADS 256

// Scratch for updated internal-node features (avoids in-place race across N-blocks)
__device__ float g_xs[(size_t)N_INTERNAL * TOK_STRIDE]; // 33.5 MB

// ----------------------------------------------------------------------------
// Projection: out[r, :] = feats[r, :] @ W_lin^T   for r in [0, MAX_LEN*BATCH)
// out layout = (token, batch, dim) flattened, row r = t*8 + b.
// ----------------------------------------------------------------------------
__global__ __launch_bounds__(NTHREADS) void proj_kernel(
    const float* __restrict__ feats,
    const float* __restrict__ Wlin,
    float* __restrict__ out)
{
    __shared__ float As[BK][BM + 4];
    __shared__ float Bs[BK][BN + 4];

    const int M = MAX_LEN * BATCH;
    const int tid = threadIdx.x;
    const int tx = tid & 15;
    const int ty = tid >> 4;
    const int bm = blockIdx.y;
    const int bn = blockIdx.x;
    const int rowBase = bm * BM;

    // Loader mapping: 256 threads load a 128x16 tile as two 64-row halves,
    // each thread does one float4 per half.
    const int lrow = tid >> 2;        // 0..63
    const int lk   = (tid & 3) * 4;   // 0,4,8,12

    const int r0 = min(rowBase + lrow,      M - 1);
    const int r1 = min(rowBase + lrow + 64, M - 1);
    const float* a0 = feats + (size_t)r0 * DM + lk;
    const float* a1 = feats + (size_t)r1 * DM + lk;
    const float* b0 = Wlin + (size_t)(bn * BN + lrow)      * DM + lk;
    const float* b1 = Wlin + (size_t)(bn * BN + lrow + 64) * DM + lk;

    float acc[TM][TN];
#pragma unroll
    for (int i = 0; i < TM; i++)
#pragma unroll
        for (int j = 0; j < TN; j++) acc[i][j] = 0.f;

    for (int kt = 0; kt < DM; kt += BK) {
        float4 av0 = *(const float4*)(a0 + kt);
        float4 av1 = *(const float4*)(a1 + kt);
        float4 bv0 = *(const float4*)(b0 + kt);
        float4 bv1 = *(const float4*)(b1 + kt);
        __syncthreads();
        As[lk + 0][lrow] = av0.x; As[lk + 1][lrow] = av0.y;
        As[lk + 2][lrow] = av0.z; As[lk + 3][lrow] = av0.w;
        As[lk + 0][lrow + 64] = av1.x; As[lk + 1][lrow + 64] = av1.y;
        As[lk + 2][lrow + 64] = av1.z; As[lk + 3][lrow + 64] = av1.w;
        Bs[lk + 0][lrow] = bv0.x; Bs[lk + 1][lrow] = bv0.y;
        Bs[lk + 2][lrow] = bv0.z; Bs[lk + 3][lrow] = bv0.w;
        Bs[lk + 0][lrow + 64] = bv1.x; Bs[lk + 1][lrow + 64] = bv1.y;
        Bs[lk + 2][lrow + 64] = bv1.z; Bs[lk + 3][lrow + 64] = bv1.w;
        __syncthreads();
#pragma unroll
        for (int kk = 0; kk < BK; kk++) {
            float4 aLo = *(const float4*)&As[kk][ty * TM];
            float4 aHi = *(const float4*)&As[kk][ty * TM + 4];
            float4 bLo = *(const float4*)&Bs[kk][tx * TN];
            float4 bHi = *(const float4*)&Bs[kk][tx * TN + 4];
            float a[TM] = {aLo.x, aLo.y, aLo.z, aLo.w, aHi.x, aHi.y, aHi.z, aHi.w};
            float b[TN] = {bLo.x, bLo.y, bLo.z, bLo.w, bHi.x, bHi.y, bHi.z, bHi.w};
#pragma unroll
            for (int i = 0; i < TM; i++)
#pragma unroll
                for (int j = 0; j < TN; j++) acc[i][j] = fmaf(a[i], b[j], acc[i][j]);
        }
    }

#pragma unroll
    for (int i = 0; i < TM; i++) {
        int r = rowBase + ty * TM + i;
        if (r < M) {
            float* o = out + (size_t)r * DM + bn * BN + tx * TN;
            *(float4*)(o)     = make_float4(acc[i][0], acc[i][1], acc[i][2], acc[i][3]);
            *(float4*)(o + 4) = make_float4(acc[i][4], acc[i][5], acc[i][6], acc[i][7]);
        }
    }
}

// ----------------------------------------------------------------------------
// Level kernel. For each parent p in [pbase, pbase+pcount):
//   m_s[b,:] = concat(x[2p+1+s], x[p], e[2p+s]) @ W_msg^T, s in {0,1}
//   x_new[p][b,:] = min(m_0, m_1)
// Logical A-row g = q*16 + b*2 + s  (pairs adjacent -> min in-register).
// Child x comes from `out` at the top level (leaves = projection values),
// from g_xs below. Parent x and e always come from `out` (projection).
// Writes go to g_xs.
// ----------------------------------------------------------------------------
__global__ __launch_bounds__(NTHREADS) void level_kernel(
    const float* __restrict__ Wmsg,
    const float* __restrict__ out,
    int pbase, int pcount, int childFromOut)
{
    __shared__ float As[BK][BM + 4];
    __shared__ float Bs[BK][BN + 4];

    const int M = pcount * 16;
    const int tid = threadIdx.x;
    const int tx = tid & 15;
    const int ty = tid >> 4;
    const int bm = blockIdx.y;
    const int bn = blockIdx.x;
    const int rowBase = bm * BM;

    const float* childSrc = childFromOut ? out : (const float*)g_xs;

    const int lrow = tid >> 2;
    const int lk   = (tid & 3) * 4;

    // Per-loader-row source pointers (3 sources each for two row halves)
    const float* src[2][3];
#pragma unroll
    for (int h = 0; h < 2; h++) {
        int g = min(rowBase + lrow + h * 64, M - 1);
        int q = g >> 4;
        int rem = g & 15;
        int b = rem >> 1;
        int s = rem & 1;
        int p = pbase + q;
        int c = 2 * p + 1 + s;
        src[h][0] = childSrc + (size_t)c * TOK_STRIDE + b * DM + lk;                 // x[child]
        src[h][1] = out + (size_t)p * TOK_STRIDE + b * DM + lk;                      // x[parent]
        src[h][2] = out + (size_t)(N_NODES + c - 1) * TOK_STRIDE + b * DM + lk;      // e[child-1]
    }
    const float* b0 = Wmsg + (size_t)(bn * BN + lrow)      * KMSG + lk;
    const float* b1 = Wmsg + (size_t)(bn * BN + lrow + 64) * KMSG + lk;

    float acc[TM][TN];
#pragma unroll
    for (int i = 0; i < TM; i++)
#pragma unroll
        for (int j = 0; j < TN; j++) acc[i][j] = 0.f;

    for (int kt = 0; kt < KMSG; kt += BK) {
        int seg = kt >> 8;            // 0,1,2 (BK=16 divides 256, tile never straddles)
        int ko = kt & 255;
        float4 av0 = *(const float4*)(src[0][seg] + ko);
        float4 av1 = *(const float4*)(src[1][seg] + ko);
        float4 bv0 = *(const float4*)(b0 + kt);
        float4 bv1 = *(const float4*)(b1 + kt);
        __syncthreads();
        As[lk + 0][lrow] = av0.x; As[lk + 1][lrow] = av0.y;
        As[lk + 2][lrow] = av0.z; As[lk + 3][lrow] = av0.w;
        As[lk + 0][lrow + 64] = av1.x; As[lk + 1][lrow + 64] = av1.y;
        As[lk + 2][lrow + 64] = av1.z; As[lk + 3][lrow + 64] = av1.w;
        Bs[lk + 0][lrow] = bv0.x; Bs[lk + 1][lrow] = bv0.y;
        Bs[lk + 2][lrow] = bv0.z; Bs[lk + 3][lrow] = bv0.w;
        Bs[lk + 0][lrow + 64] = bv1.x; Bs[lk + 1][lrow + 64] = bv1.y;
        Bs[lk + 2][lrow + 64] = bv1.z; Bs[lk + 3][lrow + 64] = bv1.w;
        __syncthreads();
#pragma unroll
        for (int kk = 0; kk < BK; kk++) {
            float4 aLo = *(const float4*)&As[kk][ty * TM];
            float4 aHi = *(const float4*)&As[kk][ty * TM + 4];
            float4 bLo = *(const float4*)&Bs[kk][tx * TN];
            float4 bHi = *(const float4*)&Bs[kk][tx * TN + 4];
            float a[TM] = {aLo.x, aLo.y, aLo.z, aLo.w, aHi.x, aHi.y, aHi.z, aHi.w};
            float b[TN] = {bLo.x, bLo.y, bLo.z, bLo.w, bHi.x, bHi.y, bHi.z, bHi.w};
#pragma unroll
            for (int i = 0; i < TM; i++)
#pragma unroll
                for (int j = 0; j < TN; j++) acc[i][j] = fmaf(a[i], b[j], acc[i][j]);
        }
    }

    // Epilogue: pairs (i, i+1) share (q, b); min across s, write x_new[p]
#pragma unroll
    for (int i = 0; i < TM; i += 2) {
        int r = rowBase + ty * TM + i;   // even
        if (r < M) {
            int q = r >> 4;
            int b = (r & 15) >> 1;
            int p = pbase + q;
            float* o = g_xs + (size_t)p * TOK_STRIDE + b * DM + bn * BN + tx * TN;
            *(float4*)(o) = make_float4(
                fminf(acc[i][0], acc[i + 1][0]), fminf(acc[i][1], acc[i + 1][1]),
                fminf(acc[i][2], acc[i + 1][2]), fminf(acc[i][3], acc[i + 1][3]));
            *(float4*)(o + 4) = make_float4(
                fminf(acc[i][4], acc[i + 1][4]), fminf(acc[i][5], acc[i + 1][5]),
                fminf(acc[i][6], acc[i + 1][6]), fminf(acc[i][7], acc[i + 1][7]));
        }
    }
}

// ----------------------------------------------------------------------------
// Final merge: internal-node x from scratch -> d_out
// ----------------------------------------------------------------------------
__global__ __launch_bounds__(256) void merge_kernel(float* __restrict__ out)
{
    size_t idx = (size_t)blockIdx.x * blockDim.x + threadIdx.x;
    const size_t n4 = (size_t)N_INTERNAL * TOK_STRIDE / 4;
    if (idx < n4) {
        ((float4*)out)[idx] = ((const float4*)g_xs)[idx];
    }
}

extern "C" void kernel_launch(void* const* d_in, const int* in_sizes, int n_in,
                              void* d_out, int out_size)
{
    const float* feats = (const float*)d_in[0];
    const float* Wlin  = (const float*)d_in[1];
    const float* Wmsg  = (const float*)d_in[2];
    // d_in[3] seg_ids, d_in[4] connectivity: tree structure is implicit, unused.
    float* out = (float*)d_out;

    dim3 blk(NTHREADS);

    {
        int M = MAX_LEN * BATCH;
        dim3 grid(DM / BN, (M + BM - 1) / BM);
        proj_kernel<<<grid, blk>>>(feats, Wlin, out);
    }

    for (int d = TREE_DEPTH - 2; d >= 0; --d) {
        int pbase = (1 << d) - 1;
        int pcount = 1 << d;
        int M = pcount * 16;
        dim3 grid(DM / BN, (M + BM - 1) / BM);
        level_kernel<<<grid, blk>>>(Wmsg, out, pbase, pcount,
                                    (d == TREE_DEPTH - 2) ? 1 : 0);
    }

    {
        size_t n4 = (size_t)N_INTERNAL * TOK_STRIDE / 4;
        int nblocks = (int)((n4 + 255) / 256);
        merge_kernel<<<nblocks, 256>>>(out);
    }
}

// round 2
// speedup vs baseline: 2.1154x; 2.1154x over previous
#include <cuda_runtime.h>
#include <cstdint>

// Problem constants
#define TREE_DEPTH 13
#define N_NODES 8191
#define N_EDGES 8190
#define MAX_LEN 16381
#define BATCH 8
#define DM 256
#define KMSG 768
#define N_INTERNAL 4095
#define TOK_STRIDE (BATCH * DM)

// Tiling
#define BM 128
#define BN 128
#define BK 16
#define NTHREADS 256
#define SPAD 8                  // smem row padding (words) -> conflict-free frag loads

__device__ float g_xs[(size_t)N_INTERNAL * TOK_STRIDE]; // 33.5 MB scratch

__device__ __forceinline__ uint32_t f2tf(float x) {
    uint32_t r;
    asm("cvt.rna.tf32.f32 %0, %1;" : "=r"(r) : "f"(x));
    return r;
}

__device__ __forceinline__ void mma_tf32(float& c0, float& c1, float& c2, float& c3,
                                         uint32_t a0, uint32_t a1, uint32_t a2, uint32_t a3,
                                         uint32_t b0, uint32_t b1) {
    asm volatile(
        "mma.sync.aligned.m16n8k8.row.col.f32.tf32.tf32.f32 "
        "{%0,%1,%2,%3}, {%4,%5,%6,%7}, {%8,%9}, {%0,%1,%2,%3};"
        : "+f"(c0), "+f"(c1), "+f"(c2), "+f"(c3)
        : "r"(a0), "r"(a1), "r"(a2), "r"(a3), "r"(b0), "r"(b1));
}

// Shared compute step: one BK=16 slab from smem buffers into acc[4][4][4]
__device__ __forceinline__ void compute_slab(
    const uint32_t (*As)[BM + SPAD], const uint32_t (*Bs)[BN + SPAD],
    int m0, int n0, int gid, int tig, float acc[4][4][4])
{
#pragma unroll
    for (int kk8 = 0; kk8 < BK; kk8 += 8) {
        uint32_t af[4][4], bf[4][2];
#pragma unroll
        for (int i = 0; i < 4; i++) {
            int m = m0 + i * 16 + gid;
            af[i][0] = As[kk8 + tig][m];
            af[i][1] = As[kk8 + tig][m + 8];
            af[i][2] = As[kk8 + tig + 4][m];
            af[i][3] = As[kk8 + tig + 4][m + 8];
        }
#pragma unroll
        for (int j = 0; j < 4; j++) {
            int n = n0 + j * 8 + gid;
            bf[j][0] = Bs[kk8 + tig][n];
            bf[j][1] = Bs[kk8 + tig + 4][n];
        }
#pragma unroll
        for (int i = 0; i < 4; i++)
#pragma unroll
            for (int j = 0; j < 4; j++)
                mma_tf32(acc[i][j][0], acc[i][j][1], acc[i][j][2], acc[i][j][3],
                         af[i][0], af[i][1], af[i][2], af[i][3], bf[j][0], bf[j][1]);
    }
}

#define STORE_A(buf, v0, v1)                                                     \
    As[buf][lk + 0][lrow] = f2tf(v0.x); As[buf][lk + 1][lrow] = f2tf(v0.y);      \
    As[buf][lk + 2][lrow] = f2tf(v0.z); As[buf][lk + 3][lrow] = f2tf(v0.w);      \
    As[buf][lk + 0][lrow + 64] = f2tf(v1.x); As[buf][lk + 1][lrow + 64] = f2tf(v1.y); \
    As[buf][lk + 2][lrow + 64] = f2tf(v1.z); As[buf][lk + 3][lrow + 64] = f2tf(v1.w);

#define STORE_B(buf, v0, v1)                                                     \
    Bs[buf][lk + 0][lrow] = f2tf(v0.x); Bs[buf][lk + 1][lrow] = f2tf(v0.y);      \
    Bs[buf][lk + 2][lrow] = f2tf(v0.z); Bs[buf][lk + 3][lrow] = f2tf(v0.w);      \
    Bs[buf][lk + 0][lrow + 64] = f2tf(v1.x); Bs[buf][lk + 1][lrow + 64] = f2tf(v1.y); \
    Bs[buf][lk + 2][lrow + 64] = f2tf(v1.z); Bs[buf][lk + 3][lrow + 64] = f2tf(v1.w);

// ----------------------------------------------------------------------------
// Projection: out = feats @ W_lin^T   (M = MAX_LEN*BATCH, K = 256)
// ----------------------------------------------------------------------------
__global__ __launch_bounds__(NTHREADS) void proj_kernel(
    const float* __restrict__ feats,
    const float* __restrict__ Wlin,
    float* __restrict__ out)
{
    __shared__ uint32_t As[2][BK][BM + SPAD];
    __shared__ uint32_t Bs[2][BK][BN + SPAD];

    const int M = MAX_LEN * BATCH;
    const int tid = threadIdx.x;
    const int lane = tid & 31;
    const int wid = tid >> 5;
    const int gid = lane >> 2;
    const int tig = lane & 3;
    const int m0 = (wid >> 2) * 64;
    const int n0 = (wid & 3) * 32;
    const int bm = blockIdx.y, bn = blockIdx.x;
    const int rowBase = bm * BM;

    const int lrow = tid >> 2;
    const int lk = (tid & 3) * 4;

    const int r0 = min(rowBase + lrow, M - 1);
    const int r1 = min(rowBase + lrow + 64, M - 1);
    const float* ap0 = feats + (size_t)r0 * DM + lk;
    const float* ap1 = feats + (size_t)r1 * DM + lk;
    const float* bp0 = Wlin + (size_t)(bn * BN + lrow) * DM + lk;
    const float* bp1 = Wlin + (size_t)(bn * BN + lrow + 64) * DM + lk;

    float acc[4][4][4];
#pragma unroll
    for (int i = 0; i < 4; i++)
#pragma unroll
        for (int j = 0; j < 4; j++)
#pragma unroll
            for (int c = 0; c < 4; c++) acc[i][j][c] = 0.f;

    // prologue
    {
        float4 av0 = *(const float4*)(ap0);
        float4 av1 = *(const float4*)(ap1);
        float4 bv0 = *(const float4*)(bp0);
        float4 bv1 = *(const float4*)(bp1);
        STORE_A(0, av0, av1)
        STORE_B(0, bv0, bv1)
    }
    __syncthreads();

    const int nK = DM / BK; // 16
    int cur = 0;
#pragma unroll 4
    for (int kt = 0; kt < nK; kt++) {
        float4 av0, av1, bv0, bv1;
        bool more = (kt + 1 < nK);
        if (more) {
            int ko = (kt + 1) * BK;
            av0 = *(const float4*)(ap0 + ko);
            av1 = *(const float4*)(ap1 + ko);
            bv0 = *(const float4*)(bp0 + ko);
            bv1 = *(const float4*)(bp1 + ko);
        }
        compute_slab(As[cur], Bs[cur], m0, n0, gid, tig, acc);
        if (more) {
            int nxt = cur ^ 1;
            STORE_A(nxt, av0, av1)
            STORE_B(nxt, bv0, bv1)
            __syncthreads();
            cur = nxt;
        }
    }

    // epilogue: c0,c1 -> row (base+gid); c2,c3 -> row (base+gid+8)
#pragma unroll
    for (int i = 0; i < 4; i++) {
        int ra = rowBase + m0 + i * 16 + gid;
        int rb = ra + 8;
        float* oa = out + (size_t)ra * DM + bn * BN + n0 + 2 * tig;
        float* ob = out + (size_t)rb * DM + bn * BN + n0 + 2 * tig;
#pragma unroll
        for (int j = 0; j < 4; j++) {
            if (ra < M) *(float2*)(oa + j * 8) = make_float2(acc[i][j][0], acc[i][j][1]);
            if (rb < M) *(float2*)(ob + j * 8) = make_float2(acc[i][j][2], acc[i][j][3]);
        }
    }
}

// ----------------------------------------------------------------------------
// Level kernel: logical row g -> tile t=g>>4 (parent q=t), j=g&15, s=j>>3, b=j&7.
// A row g = concat(x[2p+1+s], x[p], e[2p+s]); C row pairs (gid, gid+8) share
// (q,b), differ in s -> min in-thread.
// ----------------------------------------------------------------------------
__global__ __launch_bounds__(NTHREADS) void level_kernel(
    const float* __restrict__ Wmsg,
    const float* __restrict__ out,
    int pbase, int pcount, int childFromOut)
{
    __shared__ uint32_t As[2][BK][BM + SPAD];
    __shared__ uint32_t Bs[2][BK][BN + SPAD];

    const int M = pcount * 16;
    const int tid = threadIdx.x;
    const int lane = tid & 31;
    const int wid = tid >> 5;
    const int gid = lane >> 2;
    const int tig = lane & 3;
    const int m0 = (wid >> 2) * 64;
    const int n0 = (wid & 3) * 32;
    const int bm = blockIdx.y, bn = blockIdx.x;
    const int rowBase = bm * BM;

    const float* childSrc = childFromOut ? out : (const float*)g_xs;

    const int lrow = tid >> 2;
    const int lk = (tid & 3) * 4;

    const float* src[2][3];
#pragma unroll
    for (int h = 0; h < 2; h++) {
        int g = min(rowBase + lrow + h * 64, M - 1);
        int q = g >> 4;
        int j = g & 15;
        int s = j >> 3;
        int b = j & 7;
        int p = pbase + q;
        int c = 2 * p + 1 + s;
        src[h][0] = childSrc + (size_t)c * TOK_STRIDE + b * DM + lk;
        src[h][1] = out + (size_t)p * TOK_STRIDE + b * DM + lk;
        src[h][2] = out + (size_t)(N_NODES + c - 1) * TOK_STRIDE + b * DM + lk;
    }
    const float* bp0 = Wmsg + (size_t)(bn * BN + lrow) * KMSG + lk;
    const float* bp1 = Wmsg + (size_t)(bn * BN + lrow + 64) * KMSG + lk;

    float acc[4][4][4];
#pragma unroll
    for (int i = 0; i < 4; i++)
#pragma unroll
        for (int j = 0; j < 4; j++)
#pragma unroll
            for (int c = 0; c < 4; c++) acc[i][j][c] = 0.f;

    // prologue (kt=0: seg=0, ko=0)
    {
        float4 av0 = *(const float4*)(src[0][0]);
        float4 av1 = *(const float4*)(src[1][0]);
        float4 bv0 = *(const float4*)(bp0);
        float4 bv1 = *(const float4*)(bp1);
        STORE_A(0, av0, av1)
        STORE_B(0, bv0, bv1)
    }
    __syncthreads();

    const int nK = KMSG / BK; // 48
    int cur = 0;
#pragma unroll 4
    for (int kt = 0; kt < nK; kt++) {
        float4 av0, av1, bv0, bv1;
        bool more = (kt + 1 < nK);
        if (more) {
            int koff = (kt + 1) * BK;
            int seg = koff >> 8;
            int ko = koff & 255;
            av0 = *(const float4*)(src[0][seg] + ko);
            av1 = *(const float4*)(src[1][seg] + ko);
            bv0 = *(const float4*)(bp0 + koff);
            bv1 = *(const float4*)(bp1 + koff);
        }
        compute_slab(As[cur], Bs[cur], m0, n0, gid, tig, acc);
        if (more) {
            int nxt = cur ^ 1;
            STORE_A(nxt, av0, av1)
            STORE_B(nxt, bv0, bv1)
            __syncthreads();
            cur = nxt;
        }
    }

    // epilogue: min over s (c0/c1 = s=0 row, c2/c3 = s=1 row), write x_new[p]
#pragma unroll
    for (int i = 0; i < 4; i++) {
        int r = rowBase + m0 + i * 16 + gid;   // s=0 row: q=r>>4, b=r&7
        if (r < M) {
            int q = r >> 4;
            int b = r & 7;
            int p = pbase + q;
            float* o = g_xs + (size_t)p * TOK_STRIDE + b * DM + bn * BN + n0 + 2 * tig;
#pragma unroll
            for (int j = 0; j < 4; j++) {
                *(float2*)(o + j * 8) = make_float2(fminf(acc[i][j][0], acc[i][j][2]),
                                                    fminf(acc[i][j][1], acc[i][j][3]));
            }
        }
    }
}

// ----------------------------------------------------------------------------
// Final merge: internal-node x from scratch -> d_out
// ----------------------------------------------------------------------------
__global__ __launch_bounds__(256) void merge_kernel(float* __restrict__ out)
{
    size_t idx = (size_t)blockIdx.x * blockDim.x + threadIdx.x;
    const size_t n4 = (size_t)N_INTERNAL * TOK_STRIDE / 4;
    if (idx < n4) {
        ((float4*)out)[idx] = ((const float4*)g_xs)[idx];
    }
}

extern "C" void kernel_launch(void* const* d_in, const int* in_sizes, int n_in,
                              void* d_out, int out_size)
{
    const float* feats = (const float*)d_in[0];
    const float* Wlin  = (const float*)d_in[1];
    const float* Wmsg  = (const float*)d_in[2];
    float* out = (float*)d_out;

    dim3 blk(NTHREADS);

    {
        int M = MAX_LEN * BATCH;
        dim3 grid(DM / BN, (M + BM - 1) / BM);
        proj_kernel<<<grid, blk>>>(feats, Wlin, out);
    }

    for (int d = TREE_DEPTH - 2; d >= 0; --d) {
        int pbase = (1 << d) - 1;
        int pcount = 1 << d;
        int M = pcount * 16;
        dim3 grid(DM / BN, (M + BM - 1) / BM);
        level_kernel<<<grid, blk>>>(Wmsg, out, pbase, pcount,
                                    (d == TREE_DEPTH - 2) ? 1 : 0);
    }

    {
        size_t n4 = (size_t)N_INTERNAL * TOK_STRIDE / 4;
        int nblocks = (int)((n4 + 255) / 256);
        merge_kernel<<<nblocks, 256>>>(out);
    }
}

// round 3
// speedup vs baseline: 2.2137x; 1.0465x over previous
#include <cuda_runtime.h>
#include <cstdint>

// Problem constants
#define TREE_DEPTH 13
#define N_NODES 8191
#define N_EDGES 8190
#define MAX_LEN 16381
#define BATCH 8
#define DM 256
#define KMSG 768
#define N_INTERNAL 4095
#define TOK_STRIDE (BATCH * DM)

// Tiling
#define BM 128
#define BN 128
#define BK 16
#define NTHREADS 256

// Fragment-packed smem:
//  A: 8 mtiles (16 rows each) x 64 granules(16B). granule g = lane*2 + k8,
//     swizzled g' = g ^ ((g>>3)&7). Floats within granule = regs a0..a3.
//  B: 16 ntiles (8 cols each) x 32 granules(16B). granule g = lane,
//     swizzled g' = g ^ (g>>2). Floats = {b0(k8=0), b1(k8=0), b0(k8=1), b1(k8=1)}.
#define A_WORDS 2048   // 8 * 256
#define B_WORDS 2048   // 16 * 128

__device__ float g_xs[(size_t)N_INTERNAL * TOK_STRIDE]; // 33.5 MB scratch

__device__ __forceinline__ uint32_t f2tf(float x) {
    uint32_t r;
    asm("cvt.rna.tf32.f32 %0, %1;" : "=r"(r) : "f"(x));
    return r;
}

__device__ __forceinline__ void mma_tf32(float& c0, float& c1, float& c2, float& c3,
                                         uint32_t a0, uint32_t a1, uint32_t a2, uint32_t a3,
                                         uint32_t b0, uint32_t b1) {
    asm volatile(
        "mma.sync.aligned.m16n8k8.row.col.f32.tf32.tf32.f32 "
        "{%0,%1,%2,%3}, {%4,%5,%6,%7}, {%8,%9}, {%0,%1,%2,%3};"
        : "+f"(c0), "+f"(c1), "+f"(c2), "+f"(c3)
        : "r"(a0), "r"(a1), "r"(a2), "r"(a3), "r"(b0), "r"(b1));
}

// Producer address precompute. lrow in 0..63, lk in {0,4,8,12}.
// A element (m_local, lk+j) -> frag slot; B element (n_local, lk+j) -> frag slot.
struct ProdAddr {
    int a[2][4];
    int b[2][4];
};

__device__ __forceinline__ ProdAddr make_prod_addr(int lrow, int lk) {
    ProdAddr pa;
    int k8 = lk >> 3;
    int hi = (lk >> 2) & 1;
#pragma unroll
    for (int h = 0; h < 2; h++) {
        int ml = lrow + h * 64;
        int mtile = ml >> 4, mm = ml & 15;
        int regb = hi * 2 + ((mm >> 3) & 1);
#pragma unroll
        for (int j = 0; j < 4; j++) {
            int lv = (mm & 7) * 4 + j;
            int g = lv * 2 + k8;
            int gs = g ^ ((g >> 3) & 7);
            pa.a[h][j] = mtile * 256 + gs * 4 + regb;
        }
        int ntile = ml >> 3, nn = ml & 7;
#pragma unroll
        for (int j = 0; j < 4; j++) {
            int lv = nn * 4 + j;
            int gs = lv ^ (lv >> 2);
            pa.b[h][j] = ntile * 128 + gs * 4 + (k8 * 2 + hi);
        }
    }
    return pa;
}

#define STORE_A(buf, v0, v1)                               \
    As[buf][pa.a[0][0]] = f2tf(v0.x); As[buf][pa.a[0][1]] = f2tf(v0.y); \
    As[buf][pa.a[0][2]] = f2tf(v0.z); As[buf][pa.a[0][3]] = f2tf(v0.w); \
    As[buf][pa.a[1][0]] = f2tf(v1.x); As[buf][pa.a[1][1]] = f2tf(v1.y); \
    As[buf][pa.a[1][2]] = f2tf(v1.z); As[buf][pa.a[1][3]] = f2tf(v1.w);

#define STORE_B(buf, v0, v1)                               \
    Bs[buf][pa.b[0][0]] = f2tf(v0.x); Bs[buf][pa.b[0][1]] = f2tf(v0.y); \
    Bs[buf][pa.b[0][2]] = f2tf(v0.z); Bs[buf][pa.b[0][3]] = f2tf(v0.w); \
    Bs[buf][pa.b[1][0]] = f2tf(v1.x); Bs[buf][pa.b[1][1]] = f2tf(v1.y); \
    Bs[buf][pa.b[1][2]] = f2tf(v1.z); Bs[buf][pa.b[1][3]] = f2tf(v1.w);

// One BK=16 slab: 4 B-frag LDS.128, then per k8: 4 A-frag LDS.128 + 16 mma.
__device__ __forceinline__ void compute_slab(
    const uint32_t* __restrict__ As, const uint32_t* __restrict__ Bs,
    int mtb, int ntb, const int* aOff, int bOff, float acc[4][4][4])
{
    uint4 bf[4];
#pragma unroll
    for (int j = 0; j < 4; j++)
        bf[j] = *(const uint4*)&Bs[(ntb + j) * 128 + bOff];
#pragma unroll
    for (int k8 = 0; k8 < 2; k8++) {
        uint4 af[4];
#pragma unroll
        for (int i = 0; i < 4; i++)
            af[i] = *(const uint4*)&As[(mtb + i) * 256 + aOff[k8]];
#pragma unroll
        for (int i = 0; i < 4; i++)
#pragma unroll
            for (int j = 0; j < 4; j++) {
                uint32_t b0 = k8 ? bf[j].z : bf[j].x;
                uint32_t b1 = k8 ? bf[j].w : bf[j].y;
                mma_tf32(acc[i][j][0], acc[i][j][1], acc[i][j][2], acc[i][j][3],
                         af[i].x, af[i].y, af[i].z, af[i].w, b0, b1);
            }
    }
}

// ----------------------------------------------------------------------------
// Projection: out = feats @ W_lin^T   (M = MAX_LEN*BATCH, K = 256)
// ----------------------------------------------------------------------------
__global__ __launch_bounds__(NTHREADS, 2) void proj_kernel(
    const float* __restrict__ feats,
    const float* __restrict__ Wlin,
    float* __restrict__ out)
{
    __shared__ uint32_t As[2][A_WORDS];
    __shared__ uint32_t Bs[2][B_WORDS];

    const int M = MAX_LEN * BATCH;
    const int tid = threadIdx.x;
    const int lane = tid & 31;
    const int wid = tid >> 5;
    const int gid = lane >> 2;
    const int tig = lane & 3;
    const int m0 = (wid >> 2) * 64;
    const int n0 = (wid & 3) * 32;
    const int mtb = m0 >> 4, ntb = n0 >> 3;
    const int bm = blockIdx.y, bn = blockIdx.x;
    const int rowBase = bm * BM;

    const int lrow = tid >> 2;
    const int lk = (tid & 3) * 4;
    ProdAddr pa = make_prod_addr(lrow, lk);

    int aOff[2], bOff;
#pragma unroll
    for (int k8 = 0; k8 < 2; k8++) {
        int g = lane * 2 + k8;
        aOff[k8] = (g ^ ((g >> 3) & 7)) * 4;
    }
    bOff = (lane ^ (lane >> 2)) * 4;

    const int r0 = min(rowBase + lrow, M - 1);
    const int r1 = min(rowBase + lrow + 64, M - 1);
    const float* ap0 = feats + (size_t)r0 * DM + lk;
    const float* ap1 = feats + (size_t)r1 * DM + lk;
    const float* bp0 = Wlin + (size_t)(bn * BN + lrow) * DM + lk;
    const float* bp1 = Wlin + (size_t)(bn * BN + lrow + 64) * DM + lk;

    float acc[4][4][4];
#pragma unroll
    for (int i = 0; i < 4; i++)
#pragma unroll
        for (int j = 0; j < 4; j++)
#pragma unroll
            for (int c = 0; c < 4; c++) acc[i][j][c] = 0.f;

    {
        float4 av0 = *(const float4*)(ap0);
        float4 av1 = *(const float4*)(ap1);
        float4 bv0 = *(const float4*)(bp0);
        float4 bv1 = *(const float4*)(bp1);
        STORE_A(0, av0, av1)
        STORE_B(0, bv0, bv1)
    }
    __syncthreads();

    const int nK = DM / BK; // 16
    int cur = 0;
#pragma unroll 2
    for (int kt = 0; kt < nK; kt++) {
        float4 av0, av1, bv0, bv1;
        bool more = (kt + 1 < nK);
        if (more) {
            int ko = (kt + 1) * BK;
            av0 = *(const float4*)(ap0 + ko);
            av1 = *(const float4*)(ap1 + ko);
            bv0 = *(const float4*)(bp0 + ko);
            bv1 = *(const float4*)(bp1 + ko);
        }
        compute_slab(As[cur], Bs[cur], mtb, ntb, aOff, bOff, acc);
        if (more) {
            int nxt = cur ^ 1;
            STORE_A(nxt, av0, av1)
            STORE_B(nxt, bv0, bv1)
            __syncthreads();
            cur = nxt;
        }
    }

#pragma unroll
    for (int i = 0; i < 4; i++) {
        int ra = rowBase + m0 + i * 16 + gid;
        int rb = ra + 8;
        float* oa = out + (size_t)ra * DM + bn * BN + n0 + 2 * tig;
        float* ob = out + (size_t)rb * DM + bn * BN + n0 + 2 * tig;
#pragma unroll
        for (int j = 0; j < 4; j++) {
            if (ra < M) *(float2*)(oa + j * 8) = make_float2(acc[i][j][0], acc[i][j][1]);
            if (rb < M) *(float2*)(ob + j * 8) = make_float2(acc[i][j][2], acc[i][j][3]);
        }
    }
}

// ----------------------------------------------------------------------------
// Level kernel: logical row g -> tile t=g>>4 (parent q=t), j=g&15, s=j>>3, b=j&7.
// A row g = concat(x[2p+1+s], x[p], e[2p+s]); C row pairs (gid, gid+8) share
// (q,b), differ in s -> min in-thread.
// ----------------------------------------------------------------------------
__global__ __launch_bounds__(NTHREADS, 2) void level_kernel(
    const float* __restrict__ Wmsg,
    const float* __restrict__ out,
    int pbase, int pcount, int childFromOut)
{
    __shared__ uint32_t As[2][A_WORDS];
    __shared__ uint32_t Bs[2][B_WORDS];

    const int M = pcount * 16;
    const int tid = threadIdx.x;
    const int lane = tid & 31;
    const int wid = tid >> 5;
    const int gid = lane >> 2;
    const int tig = lane & 3;
    const int m0 = (wid >> 2) * 64;
    const int n0 = (wid & 3) * 32;
    const int mtb = m0 >> 4, ntb = n0 >> 3;
    const int bm = blockIdx.y, bn = blockIdx.x;
    const int rowBase = bm * BM;

    const float* childSrc = childFromOut ? out : (const float*)g_xs;

    const int lrow = tid >> 2;
    const int lk = (tid & 3) * 4;
    ProdAddr pa = make_prod_addr(lrow, lk);

    int aOff[2], bOff;
#pragma unroll
    for (int k8 = 0; k8 < 2; k8++) {
        int g = lane * 2 + k8;
        aOff[k8] = (g ^ ((g >> 3) & 7)) * 4;
    }
    bOff = (lane ^ (lane >> 2)) * 4;

    const float* src[2][3];
#pragma unroll
    for (int h = 0; h < 2; h++) {
        int g = min(rowBase + lrow + h * 64, M - 1);
        int q = g >> 4;
        int j = g & 15;
        int s = j >> 3;
        int b = j & 7;
        int p = pbase + q;
        int c = 2 * p + 1 + s;
        src[h][0] = childSrc + (size_t)c * TOK_STRIDE + b * DM + lk;
        src[h][1] = out + (size_t)p * TOK_STRIDE + b * DM + lk;
        src[h][2] = out + (size_t)(N_NODES + c - 1) * TOK_STRIDE + b * DM + lk;
    }
    const float* bp0 = Wmsg + (size_t)(bn * BN + lrow) * KMSG + lk;
    const float* bp1 = Wmsg + (size_t)(bn * BN + lrow + 64) * KMSG + lk;

    float acc[4][4][4];
#pragma unroll
    for (int i = 0; i < 4; i++)
#pragma unroll
        for (int j = 0; j < 4; j++)
#pragma unroll
            for (int c = 0; c < 4; c++) acc[i][j][c] = 0.f;

    {
        float4 av0 = *(const float4*)(src[0][0]);
        float4 av1 = *(const float4*)(src[1][0]);
        float4 bv0 = *(const float4*)(bp0);
        float4 bv1 = *(const float4*)(bp1);
        STORE_A(0, av0, av1)
        STORE_B(0, bv0, bv1)
    }
    __syncthreads();

    const int nK = KMSG / BK; // 48
    int cur = 0;
#pragma unroll 2
    for (int kt = 0; kt < nK; kt++) {
        float4 av0, av1, bv0, bv1;
        bool more = (kt + 1 < nK);
        if (more) {
            int koff = (kt + 1) * BK;
            int seg = koff >> 8;
            int ko = koff & 255;
            av0 = *(const float4*)(src[0][seg] + ko);
            av1 = *(const float4*)(src[1][seg] + ko);
            bv0 = *(const float4*)(bp0 + koff);
            bv1 = *(const float4*)(bp1 + koff);
        }
        compute_slab(As[cur], Bs[cur], mtb, ntb, aOff, bOff, acc);
        if (more) {
            int nxt = cur ^ 1;
            STORE_A(nxt, av0, av1)
            STORE_B(nxt, bv0, bv1)
            __syncthreads();
            cur = nxt;
        }
    }

    // epilogue: min over s (c0/c1 = s=0 row, c2/c3 = s=1 row), write x_new[p]
#pragma unroll
    for (int i = 0; i < 4; i++) {
        int r = rowBase + m0 + i * 16 + gid;
        if (r < M) {
            int q = r >> 4;
            int b = r & 7;
            int p = pbase + q;
            float* o = g_xs + (size_t)p * TOK_STRIDE + b * DM + bn * BN + n0 + 2 * tig;
#pragma unroll
            for (int j = 0; j < 4; j++) {
                *(float2*)(o + j * 8) = make_float2(fminf(acc[i][j][0], acc[i][j][2]),
                                                    fminf(acc[i][j][1], acc[i][j][3]));
            }
        }
    }
}

// ----------------------------------------------------------------------------
// Final merge: internal-node x from scratch -> d_out
// ----------------------------------------------------------------------------
__global__ __launch_bounds__(256) void merge_kernel(float* __restrict__ out)
{
    size_t idx = (size_t)blockIdx.x * blockDim.x + threadIdx.x;
    const size_t n4 = (size_t)N_INTERNAL * TOK_STRIDE / 4;
    if (idx < n4) {
        ((float4*)out)[idx] = ((const float4*)g_xs)[idx];
    }
}

extern "C" void kernel_launch(void* const* d_in, const int* in_sizes, int n_in,
                              void* d_out, int out_size)
{
    const float* feats = (const float*)d_in[0];
    const float* Wlin  = (const float*)d_in[1];
    const float* Wmsg  = (const float*)d_in[2];
    float* out = (float*)d_out;

    dim3 blk(NTHREADS);

    {
        int M = MAX_LEN * BATCH;
        dim3 grid(DM / BN, (M + BM - 1) / BM);
        proj_kernel<<<grid, blk>>>(feats, Wlin, out);
    }

    for (int d = TREE_DEPTH - 2; d >= 0; --d) {
        int pbase = (1 << d) - 1;
        int pcount = 1 << d;
        int M = pcount * 16;
        dim3 grid(DM / BN, (M + BM - 1) / BM);
        level_kernel<<<grid, blk>>>(Wmsg, out, pbase, pcount,
                                    (d == TREE_DEPTH - 2) ? 1 : 0);
    }

    {
        size_t n4 = (size_t)N_INTERNAL * TOK_STRIDE / 4;
        int nblocks = (int)((n4 + 255) / 256);
        merge_kernel<<<nblocks, 256>>>(out);
    }
}

// round 7
// speedup vs baseline: 3.1158x; 1.4075x over previous
#include <cuda_runtime.h>
#include <cstdint>

// ---------------------------------------------------------------------------
// Problem constants
// ---------------------------------------------------------------------------
#define TREE_DEPTH 13
#define N_NODES 8191
#define MAX_LEN 16381
#define DM 256
#define KMSG 768
#define TOK 2048                  // 8 * 256 floats per token
#define MTOT (MAX_LEN * 8)        // 131048 projection rows
#define N_INTERNAL 4095
#define RS 36                     // smem row stride in floats (bank-conflict-free)

__device__ float g_xs[(size_t)N_INTERNAL * TOK];   // internal-node x scratch (33.5 MB)
__device__ float g_wlin[DM * DM];                  // rna-tf32 Wlin
__device__ float g_wmsg[DM * KMSG];                // rna-tf32 Wmsg

// ---------------------------------------------------------------------------
// Helpers
// ---------------------------------------------------------------------------
__device__ __forceinline__ uint32_t f2tf(float x) {
    uint32_t r;
    asm("cvt.rna.tf32.f32 %0, %1;" : "=r"(r) : "f"(x));
    return r;
}

__device__ __forceinline__ void cp16(uint32_t dst, const void* src) {
    asm volatile("cp.async.cg.shared.global [%0], [%1], 16;" :: "r"(dst), "l"(src) : "memory");
}
__device__ __forceinline__ void cp_commit() {
    asm volatile("cp.async.commit_group;" ::: "memory");
}
template<int N> __device__ __forceinline__ void cp_wait() {
    asm volatile("cp.async.wait_group %0;" :: "n"(N) : "memory");
}

__device__ __forceinline__ void mma_tf32(float& c0, float& c1, float& c2, float& c3,
                                         uint32_t a0, uint32_t a1, uint32_t a2, uint32_t a3,
                                         uint32_t b0, uint32_t b1) {
    asm volatile(
        "mma.sync.aligned.m16n8k8.row.col.f32.tf32.tf32.f32 "
        "{%0,%1,%2,%3}, {%4,%5,%6,%7}, {%8,%9}, {%0,%1,%2,%3};"
        : "+f"(c0), "+f"(c1), "+f"(c2), "+f"(c3)
        : "r"(a0), "r"(a1), "r"(a2), "r"(a3), "r"(b0), "r"(b1));
}

// ---------------------------------------------------------------------------
// Weight pre-conversion to rna-tf32 (stored as fp32 bit pattern)
// ---------------------------------------------------------------------------
__global__ void prep_w_kernel(const float* __restrict__ Wlin, const float* __restrict__ Wmsg)
{
    int i = blockIdx.x * blockDim.x + threadIdx.x;
    if (i < DM * DM)   g_wlin[i] = __uint_as_float(f2tf(Wlin[i]));
    if (i < DM * KMSG) g_wmsg[i] = __uint_as_float(f2tf(Wmsg[i]));
}

// ---------------------------------------------------------------------------
// Unified GEMM kernel (cp.async multistage, mma.sync tf32).
//  LEVEL=false: dst[r,:] = Aproj[r,:] @ Wlin^T          (proj)
//  LEVEL=true : row g: q=g>>4, j=g&15, s=j>>3, b=j&7, p=pbase+q, c=2p+1+s
//               A row g = concat(x[c], x[p], e[c-1]); C pairs (gid, gid+8)
//               share (q,b), differ in s -> min in-thread; write g_xs[p].
// Requires NTHR == 2*BM == 2*BN (big) / covers rows with 2 thr/row (small).
// ---------------------------------------------------------------------------
template<int BM, int BN, int NTHR, int WNW, int STAGES, bool LEVEL>
__global__ __launch_bounds__(NTHR, (BM == 128 ? 2 : 3))
void gemm_k(const float* __restrict__ Aproj,   // proj: feats (unused for LEVEL)
            float* __restrict__ outBuf,        // proj: dst; LEVEL: x_parent/e (+child at top)
            int M, int K, int pbase, int childFromOut)
{
    constexpr int MW = (NTHR / 32) / WNW;        // warps along M
    constexpr int MT = BM / (16 * MW);           // 16-row mtiles per warp
    constexpr int STG_FLT = (BM + BN) * RS;      // floats per stage
    extern __shared__ float sm[];
    const uint32_t smBase = (uint32_t)__cvta_generic_to_shared(sm);

    const int tid = threadIdx.x, lane = tid & 31, wid = tid >> 5;
    const int gid = lane >> 2, tig = lane & 3;
    const int m0 = (wid / WNW) * (MT * 16);
    const int n0 = (wid % WNW) * 32;
    const int bn = blockIdx.x;
    const int rowBase = blockIdx.y * BM;

    const float* W = LEVEL ? g_wmsg : g_wlin;

    // ---- loader setup: thread t loads A row t>>1 and B row t>>1, 64B each ----
    const int ra = tid >> 1;
    const int coff = (tid & 1) * 16;
    const float* asrc[3];
    if (LEVEL) {
        const float* childRO = childFromOut ? (const float*)outBuf : (const float*)g_xs;
        int g = min(rowBase + ra, M - 1);
        int q = g >> 4, j = g & 15, s = j >> 3, b = j & 7;
        int p = pbase + q, c = 2 * p + 1 + s;
        asrc[0] = childRO + (size_t)c * TOK + b * DM;                       // x[child]
        asrc[1] = outBuf + (size_t)p * TOK + b * DM;                        // x[parent]
        asrc[2] = outBuf + (size_t)(N_NODES + c - 1) * TOK + b * DM;        // e[child-1]
    } else {
        int g = min(rowBase + ra, M - 1);
        asrc[0] = asrc[1] = asrc[2] = Aproj + (size_t)g * DM;
    }
    const float* bsrc = W + (size_t)(bn * BN + ra) * K;

    const int nslab = K >> 5;

    auto load_stage = [&](int slab, int buf) {
        int kg = slab << 5;
        const float* a = asrc[kg >> 8] + (kg & 255) + coff;
        const float* b = bsrc + kg + coff;
        uint32_t da = smBase + (uint32_t)(buf * STG_FLT + ra * RS + coff) * 4u;
        uint32_t db = smBase + (uint32_t)(buf * STG_FLT + BM * RS + ra * RS + coff) * 4u;
#pragma unroll
        for (int i = 0; i < 4; i++) { cp16(da + i * 16, a + i * 4); cp16(db + i * 16, b + i * 4); }
        cp_commit();
    };

#pragma unroll
    for (int s = 0; s < STAGES - 1; s++) load_stage(s, s);

    float acc[MT][4][4];
#pragma unroll
    for (int mt = 0; mt < MT; mt++)
#pragma unroll
        for (int nt = 0; nt < 4; nt++)
#pragma unroll
            for (int c = 0; c < 4; c++) acc[mt][nt][c] = 0.f;

    for (int s = 0; s < nslab; s++) {
        cp_wait<STAGES - 2>();
        __syncthreads();
        const uint32_t* As = (const uint32_t*)sm + (s % STAGES) * STG_FLT;
        const uint32_t* Bs = As + BM * RS;
#pragma unroll
        for (int k8 = 0; k8 < 4; k8++) {
            const int kb = k8 * 8;
            uint32_t a[MT][4];
#pragma unroll
            for (int mt = 0; mt < MT; mt++) {
                int r0 = (m0 + mt * 16 + gid) * RS + kb + tig;
                a[mt][0] = As[r0];
                a[mt][1] = As[r0 + 8 * RS];
                a[mt][2] = As[r0 + 4];
                a[mt][3] = As[r0 + 8 * RS + 4];
            }
            uint32_t b[4][2];
#pragma unroll
            for (int nt = 0; nt < 4; nt++) {
                int rb = (n0 + nt * 8 + gid) * RS + kb + tig;
                b[nt][0] = Bs[rb];
                b[nt][1] = Bs[rb + 4];
            }
#pragma unroll
            for (int mt = 0; mt < MT; mt++)
#pragma unroll
                for (int nt = 0; nt < 4; nt++)
                    mma_tf32(acc[mt][nt][0], acc[mt][nt][1], acc[mt][nt][2], acc[mt][nt][3],
                             a[mt][0], a[mt][1], a[mt][2], a[mt][3], b[nt][0], b[nt][1]);
        }
        __syncthreads();
        int nx = s + STAGES - 1;
        if (nx < nslab) load_stage(nx, nx % STAGES);
        else cp_commit();
    }

    // ---- epilogue ----
    if (!LEVEL) {
#pragma unroll
        for (int mt = 0; mt < MT; mt++) {
            int r = rowBase + m0 + mt * 16 + gid;
#pragma unroll
            for (int nt = 0; nt < 4; nt++) {
                int ncol = bn * BN + n0 + nt * 8 + 2 * tig;
                if (r < M)
                    *(float2*)(outBuf + (size_t)r * DM + ncol) =
                        make_float2(acc[mt][nt][0], acc[mt][nt][1]);
                if (r + 8 < M)
                    *(float2*)(outBuf + (size_t)(r + 8) * DM + ncol) =
                        make_float2(acc[mt][nt][2], acc[mt][nt][3]);
            }
        }
    } else {
#pragma unroll
        for (int mt = 0; mt < MT; mt++) {
            int r = rowBase + m0 + mt * 16 + gid;   // s=0 row (r&15 = gid < 8)
            if (r < M) {
                int p = pbase + (r >> 4), b = r & 7;
                float* o = g_xs + (size_t)p * TOK + b * DM + bn * BN + n0 + 2 * tig;
#pragma unroll
                for (int nt = 0; nt < 4; nt++)
                    *(float2*)(o + nt * 8) =
                        make_float2(fminf(acc[mt][nt][0], acc[mt][nt][2]),
                                    fminf(acc[mt][nt][1], acc[mt][nt][3]));
            }
        }
    }
}

// ---------------------------------------------------------------------------
// Final merge: internal-node x scratch -> d_out
// ---------------------------------------------------------------------------
__global__ __launch_bounds__(256) void merge_kernel(float* __restrict__ out)
{
    size_t idx = (size_t)blockIdx.x * blockDim.x + threadIdx.x;
    const size_t n4 = (size_t)N_INTERNAL * TOK / 4;
    if (idx < n4) ((float4*)out)[idx] = ((const float4*)g_xs)[idx];
}

// ---------------------------------------------------------------------------
#define SMEM_BIG   (3 * (128 + 128) * RS * 4)   // 110592 B
#define SMEM_SMALL (4 * (64 + 64) * RS * 4)     //  73728 B

extern "C" void kernel_launch(void* const* d_in, const int* in_sizes, int n_in,
                              void* d_out, int out_size)
{
    const float* feats = (const float*)d_in[0];
    const float* Wlin  = (const float*)d_in[1];
    const float* Wmsg  = (const float*)d_in[2];
    float* out = (float*)d_out;

    (void)cudaFuncSetAttribute((const void*)gemm_k<128, 128, 256, 4, 3, false>,
                               cudaFuncAttributeMaxDynamicSharedMemorySize, SMEM_BIG);
    (void)cudaFuncSetAttribute((const void*)gemm_k<128, 128, 256, 4, 3, true>,
                               cudaFuncAttributeMaxDynamicSharedMemorySize, SMEM_BIG);
    (void)cudaFuncSetAttribute((const void*)gemm_k<64, 64, 128, 2, 4, true>,
                               cudaFuncAttributeMaxDynamicSharedMemorySize, SMEM_SMALL);

    // 1) weights -> rna tf32
    prep_w_kernel<<<(DM * KMSG + 255) / 256, 256>>>(Wlin, Wmsg);

    // 2) projection: out = feats @ Wlin^T
    {
        dim3 grid(DM / 128, (MTOT + 127) / 128);   // (2, 1024)
        gemm_k<128, 128, 256, 4, 3, false><<<grid, 256, SMEM_BIG>>>(
            feats, out, MTOT, DM, 0, 0);
    }

    // 3) tree levels
    for (int d = TREE_DEPTH - 2; d >= 0; --d) {
        int pbase = (1 << d) - 1;
        int pcount = 1 << d;
        int M = pcount * 16;
        int cfo = (d == TREE_DEPTH - 2) ? 1 : 0;
        if (d >= 10) {
            dim3 grid(DM / 128, (M + 127) / 128);
            gemm_k<128, 128, 256, 4, 3, true><<<grid, 256, SMEM_BIG>>>(
                feats, out, M, KMSG, pbase, cfo);
        } else {
            dim3 grid(DM / 64, (M + 63) / 64);
            gemm_k<64, 64, 128, 2, 4, true><<<grid, 128, SMEM_SMALL>>>(
                feats, out, M, KMSG, pbase, cfo);
        }
    }

    // 4) merge internal-node x into d_out
    {
        size_t n4 = (size_t)N_INTERNAL * TOK / 4;
        merge_kernel<<<(int)((n4 + 255) / 256), 256>>>(out);
    }
}